// round 1
// baseline (speedup 1.0000x reference)
#include <cuda_runtime.h>
#include <math.h>

#define BB 8
#define SS 4096
#define DD 768
#define MM 64
#define FF 3072
#define HH 12
#define HD 64
#define EPSF 1e-5f

// ---------------- scratch (device globals; no allocations allowed) ----------
__device__ float g_sl[MM * DD];            // l2norm(slots)*scale
__device__ float g_xn[BB * SS * DD];       // rms-normed x
__device__ float g_rn[BB * SS];            // 1/max(||xn_token||, eps)
__device__ float g_logits[(size_t)BB * HH * MM * SS]; // shared by dispatch & combine
__device__ float g_rmax[BB * HH * MM];
__device__ float g_rsum[BB * HH * MM];
__device__ float g_y[BB * MM * DD];        // dispatched slot inputs
__device__ float g_hid[(size_t)BB * MM * FF];
__device__ float g_y2[BB * MM * DD];       // expert outputs

// ---------------- K0: slots -> l2norm * scale --------------------------------
__global__ void k_slots(const float* __restrict__ slots, const float* __restrict__ scale) {
    int m = blockIdx.x;
    int tid = threadIdx.x;
    __shared__ float red[8];
    float ss = 0.f;
    for (int i = tid; i < DD; i += 256) {
        float v = slots[m * DD + i];
        ss += v * v;
    }
    for (int o = 16; o; o >>= 1) ss += __shfl_down_sync(~0u, ss, o);
    if ((tid & 31) == 0) red[tid >> 5] = ss;
    __syncthreads();
    if (tid < 32) {
        float s2 = (tid < 8) ? red[tid] : 0.f;
        for (int o = 4; o; o >>= 1) s2 += __shfl_down_sync(~0u, s2, o);
        if (tid == 0) red[0] = s2;
    }
    __syncthreads();
    float inv = scale[m] / fmaxf(sqrtf(red[0]), EPSF);
    for (int i = tid; i < DD; i += 256) g_sl[m * DD + i] = slots[m * DD + i] * inv;
}

// ---------------- K1: rmsnorm + per-token l2 inverse norm --------------------
__global__ void k_norm(const float* __restrict__ x, const float* __restrict__ nw) {
    int t = blockIdx.x;           // token index in [0, B*S)
    int tid = threadIdx.x;        // 256 threads, 3 elements each
    __shared__ float red[8];
    const float* xr = x + (size_t)t * DD;
    float v0 = xr[tid], v1 = xr[tid + 256], v2 = xr[tid + 512];
    float ss = v0 * v0 + v1 * v1 + v2 * v2;
    for (int o = 16; o; o >>= 1) ss += __shfl_down_sync(~0u, ss, o);
    if ((tid & 31) == 0) red[tid >> 5] = ss;
    __syncthreads();
    if (tid < 32) {
        float s2 = (tid < 8) ? red[tid] : 0.f;
        for (int o = 4; o; o >>= 1) s2 += __shfl_down_sync(~0u, s2, o);
        if (tid == 0) red[0] = s2;
    }
    __syncthreads();
    float rstd = rsqrtf(red[0] / (float)DD + EPSF);
    __syncthreads();
    float a0 = v0 * rstd * nw[tid];
    float a1 = v1 * rstd * nw[tid + 256];
    float a2 = v2 * rstd * nw[tid + 512];
    float* xo = g_xn + (size_t)t * DD;
    xo[tid] = a0; xo[tid + 256] = a1; xo[tid + 512] = a2;
    float s2 = a0 * a0 + a1 * a1 + a2 * a2;
    for (int o = 16; o; o >>= 1) s2 += __shfl_down_sync(~0u, s2, o);
    if ((tid & 31) == 0) red[tid >> 5] = s2;
    __syncthreads();
    if (tid == 0) {
        float t2 = 0.f;
        for (int i = 0; i < 8; i++) t2 += red[i];
        g_rn[t] = 1.f / fmaxf(sqrtf(t2), EPSF);
    }
}

// ---------------- K2: logits[b,h,m,s] = slh . (xn * rn) ----------------------
__global__ void k_logits() {
    // grid (S/128, H, B), 128 threads: one token per thread
    int s = blockIdx.x * 128 + threadIdx.x;
    int h = blockIdx.y, b = blockIdx.z;
    __shared__ float4 sl4[MM][HD / 4];   // 16KB
    for (int i = threadIdx.x; i < MM * (HD / 4); i += 128) {
        int m = i / (HD / 4), d4 = i % (HD / 4);
        sl4[m][d4] = *(const float4*)&g_sl[m * DD + h * HD + d4 * 4];
    }
    __syncthreads();
    float rn = g_rn[b * SS + s];
    float4 tok[16];
    const float* xp = &g_xn[((size_t)(b * SS + s)) * DD + h * HD];
#pragma unroll
    for (int i = 0; i < 16; i++) {
        float4 v = *(const float4*)(xp + i * 4);
        v.x *= rn; v.y *= rn; v.z *= rn; v.w *= rn;
        tok[i] = v;
    }
    size_t lbase = (size_t)((b * HH + h) * MM) * SS + s;
    for (int m = 0; m < MM; m++) {
        float dot = 0.f;
#pragma unroll
        for (int i = 0; i < 16; i++) {
            float4 sv = sl4[m][i];
            dot += tok[i].x * sv.x + tok[i].y * sv.y + tok[i].z * sv.z + tok[i].w * sv.w;
        }
        g_logits[lbase + (size_t)m * SS] = dot;
    }
}

// ---------------- K3: per-(b,h,m) row max / sum(exp) over s -------------------
__global__ void k_stats() {
    int r = blockIdx.x;
    int tid = threadIdx.x;
    const float* row = g_logits + (size_t)r * SS;
    __shared__ float red[8];
    float mx = -1e30f;
    for (int i = tid; i < SS; i += 256) mx = fmaxf(mx, row[i]);
    for (int o = 16; o; o >>= 1) mx = fmaxf(mx, __shfl_down_sync(~0u, mx, o));
    if ((tid & 31) == 0) red[tid >> 5] = mx;
    __syncthreads();
    if (tid < 32) {
        float m2 = (tid < 8) ? red[tid] : -1e30f;
        for (int o = 4; o; o >>= 1) m2 = fmaxf(m2, __shfl_down_sync(~0u, m2, o));
        if (tid == 0) red[0] = m2;
    }
    __syncthreads();
    float gmx = red[0];
    __syncthreads();
    float sm = 0.f;
    for (int i = tid; i < SS; i += 256) sm += __expf(row[i] - gmx);
    for (int o = 16; o; o >>= 1) sm += __shfl_down_sync(~0u, sm, o);
    if ((tid & 31) == 0) red[tid >> 5] = sm;
    __syncthreads();
    if (tid == 0) {
        float s = 0.f;
        for (int i = 0; i < 8; i++) s += red[i];
        g_rmax[r] = gmx;
        g_rsum[r] = s;
    }
}

__global__ void k_zero() { g_y[blockIdx.x * 256 + threadIdx.x] = 0.f; }

// ---------------- K4: dispatch weighted sum -> y[b,m,D] ----------------------
__global__ void k_disp() {
    // grid (4 s-chunks, H, B), 256 threads
    int ch = blockIdx.x, h = blockIdx.y, b = blockIdx.z;
    int tid = threadIdx.x;
    int g = tid >> 6;        // m group (16 slots each)
    int d = tid & 63;        // head dim
    __shared__ float pT[64][68];   // [s][m] transposed probs, padded
    __shared__ float xt[64][64];   // [s][d]
    __shared__ float smax[MM], sinv[MM];
    if (tid < MM) {
        int r = (b * HH + h) * MM + tid;
        smax[tid] = g_rmax[r];
        sinv[tid] = 1.f / g_rsum[r];
    }
    float acc[16];
#pragma unroll
    for (int j = 0; j < 16; j++) acc[j] = 0.f;
    const int CH = SS / 4;
    int s0c = ch * CH;
    size_t lbh = (size_t)((b * HH + h) * MM) * SS;
    for (int tile = 0; tile < CH / 64; tile++) {
        int s0 = s0c + tile * 64;
        __syncthreads();
        for (int i = tid; i < MM * 64; i += 256) {
            int m = i >> 6, s = i & 63;
            float l = g_logits[lbh + (size_t)m * SS + (s0 + s)];
            pT[s][m] = __expf(l - smax[m]) * sinv[m];
        }
        for (int i = tid; i < 64 * 64; i += 256) {
            int s = i >> 6, dd2 = i & 63;
            xt[s][dd2] = g_xn[((size_t)(b * SS + s0 + s)) * DD + h * HD + dd2];
        }
        __syncthreads();
        for (int s = 0; s < 64; s++) {
            float xv = xt[s][d];
            const float4* pp = (const float4*)&pT[s][g << 4];
            float4 p0 = pp[0], p1 = pp[1], p2 = pp[2], p3 = pp[3];
            acc[0]  += p0.x * xv; acc[1]  += p0.y * xv; acc[2]  += p0.z * xv; acc[3]  += p0.w * xv;
            acc[4]  += p1.x * xv; acc[5]  += p1.y * xv; acc[6]  += p1.z * xv; acc[7]  += p1.w * xv;
            acc[8]  += p2.x * xv; acc[9]  += p2.y * xv; acc[10] += p2.z * xv; acc[11] += p2.w * xv;
            acc[12] += p3.x * xv; acc[13] += p3.y * xv; acc[14] += p3.z * xv; acc[15] += p3.w * xv;
        }
    }
#pragma unroll
    for (int j = 0; j < 16; j++) {
        int m = (g << 4) + j;
        atomicAdd(&g_y[((size_t)(b * MM + m)) * DD + h * HD + d], acc[j]);
    }
}

// ---------------- K5: fc1 + exact GELU ---------------------------------------
__global__ void k_fc1(const float* __restrict__ w1, const float* __restrict__ b1) {
    // grid (FF/256, M), 256 threads: one output column f per thread, 8 batch rows
    int m = blockIdx.y;
    int f = blockIdx.x * 256 + threadIdx.x;
    __shared__ float ys[8][DD];    // 24KB
    for (int i = threadIdx.x; i < 8 * DD; i += 256) {
        int b = i / DD, k = i % DD;
        ys[b][k] = g_y[((size_t)(b * MM + m)) * DD + k];
    }
    __syncthreads();
    float bias = b1[m * FF + f];
    float acc[8];
#pragma unroll
    for (int b = 0; b < 8; b++) acc[b] = bias;
    const float* wp = w1 + (size_t)m * DD * FF + f;
    for (int k4 = 0; k4 < DD / 4; k4++) {
        float4 yv[8];
#pragma unroll
        for (int b = 0; b < 8; b++) yv[b] = *(const float4*)&ys[b][k4 * 4];
#pragma unroll
        for (int kk = 0; kk < 4; kk++) {
            float w = wp[(size_t)(k4 * 4 + kk) * FF];
            const float* yk = (const float*)yv;
#pragma unroll
            for (int b = 0; b < 8; b++) acc[b] += ((const float*)&yv[b])[kk] * w;
            (void)yk;
        }
    }
#pragma unroll
    for (int b = 0; b < 8; b++) {
        float v = acc[b];
        float ge = 0.5f * v * (1.f + erff(v * 0.70710678118654752f));
        g_hid[((size_t)(b * MM + m)) * FF + f] = ge;
    }
}

// ---------------- K6: fc2 -----------------------------------------------------
__global__ void k_fc2(const float* __restrict__ w2, const float* __restrict__ b2) {
    // grid (D/128, M), 128 threads
    int m = blockIdx.y;
    int d = blockIdx.x * 128 + threadIdx.x;
    __shared__ float hs[8][768];   // 24KB k-chunk
    float bias = b2[m * DD + d];
    float acc[8];
#pragma unroll
    for (int b = 0; b < 8; b++) acc[b] = bias;
    const float* wp = w2 + (size_t)m * FF * DD + d;
    for (int kc = 0; kc < FF; kc += 768) {
        __syncthreads();
        for (int i = threadIdx.x; i < 8 * 768; i += 128) {
            int b = i / 768, k = i % 768;
            hs[b][k] = g_hid[((size_t)(b * MM + m)) * FF + kc + k];
        }
        __syncthreads();
        for (int k4 = 0; k4 < 192; k4++) {
            float4 yv[8];
#pragma unroll
            for (int b = 0; b < 8; b++) yv[b] = *(const float4*)&hs[b][k4 * 4];
#pragma unroll
            for (int kk = 0; kk < 4; kk++) {
                float w = wp[(size_t)(kc + k4 * 4 + kk) * DD];
#pragma unroll
                for (int b = 0; b < 8; b++) acc[b] += ((const float*)&yv[b])[kk] * w;
            }
        }
    }
#pragma unroll
    for (int b = 0; b < 8; b++) g_y2[((size_t)(b * MM + m)) * DD + d] = acc[b];
}

// ---------------- K7: combine (softmax over m, length 64) --------------------
__global__ void k_comb(float* __restrict__ out) {
    // grid (S/128, H, B), 128 threads: one token per thread
    int s = blockIdx.x * 128 + threadIdx.x;
    int h = blockIdx.y, b = blockIdx.z;
    __shared__ float4 y2s[MM][HD / 4];  // 16KB expert-output tile for this (b,h)
    for (int i = threadIdx.x; i < MM * (HD / 4); i += 128) {
        int m = i / (HD / 4), d4 = i % (HD / 4);
        y2s[m][d4] = *(const float4*)&g_y2[((size_t)(b * MM + m)) * DD + h * HD + d4 * 4];
    }
    __syncthreads();
    float l[MM];
    size_t lbase = (size_t)((b * HH + h) * MM) * SS + s;
    float mx = -1e30f;
#pragma unroll
    for (int m = 0; m < MM; m++) {
        l[m] = g_logits[lbase + (size_t)m * SS];
        mx = fmaxf(mx, l[m]);
    }
    float sm = 0.f;
#pragma unroll
    for (int m = 0; m < MM; m++) {
        l[m] = __expf(l[m] - mx);
        sm += l[m];
    }
    float inv = 1.f / sm;
    float* op = out + ((size_t)(b * SS + s)) * DD + h * HD;
#pragma unroll 1
    for (int d4 = 0; d4 < HD / 4; d4++) {
        float4 a = make_float4(0.f, 0.f, 0.f, 0.f);
#pragma unroll
        for (int m = 0; m < MM; m++) {
            float4 yv = y2s[m][d4];
            float p = l[m];
            a.x += p * yv.x; a.y += p * yv.y; a.z += p * yv.z; a.w += p * yv.w;
        }
        a.x *= inv; a.y *= inv; a.z *= inv; a.w *= inv;
        *(float4*)(op + d4 * 4) = a;
    }
}

// ---------------- launch ------------------------------------------------------
extern "C" void kernel_launch(void* const* d_in, const int* in_sizes, int n_in,
                              void* d_out, int out_size) {
    const float* x      = (const float*)d_in[0];
    const float* slots  = (const float*)d_in[1];
    const float* scale  = (const float*)d_in[2];
    const float* fc1_w  = (const float*)d_in[3];
    const float* fc1_b  = (const float*)d_in[4];
    const float* fc2_w  = (const float*)d_in[5];
    const float* fc2_b  = (const float*)d_in[6];
    const float* norm_w = (const float*)d_in[7];
    float* out = (float*)d_out;

    k_slots<<<MM, 256>>>(slots, scale);
    k_norm<<<BB * SS, 256>>>(x, norm_w);
    k_logits<<<dim3(SS / 128, HH, BB), 128>>>();
    k_stats<<<BB * HH * MM, 256>>>();
    k_zero<<<(BB * MM * DD) / 256, 256>>>();
    k_disp<<<dim3(4, HH, BB), 256>>>();
    k_fc1<<<dim3(FF / 256, MM), 256>>>(fc1_w, fc1_b);
    k_fc2<<<dim3(DD / 128, MM), 128>>>(fc2_w, fc2_b);
    k_comb<<<dim3(SS / 128, HH, BB), 128>>>(out);
}

// round 2
// speedup vs baseline: 1.7637x; 1.7637x over previous
#include <cuda_runtime.h>
#include <cuda_fp16.h>
#include <math.h>

#define BB 8
#define SS 4096
#define DD 768
#define MM 64
#define FF 3072
#define HH 12
#define HD 64
#define EPSF 1e-5f

// ---------------- scratch -----------------------------------------------------
__device__ float  g_sl[MM * DD];
__device__ float  g_xn[BB * SS * DD];
__device__ float  g_rn[BB * SS];
__device__ __half g_lh[(size_t)BB * HH * MM * SS];   // logits, fp16
__device__ float  g_rmax[BB * HH * MM];
__device__ float  g_rsum[BB * HH * MM];
__device__ float  g_y[BB * MM * DD];
__device__ float  g_hid[(size_t)BB * MM * FF];
__device__ float  g_y2[BB * MM * DD];

// ---------------- K0: slots ---------------------------------------------------
__global__ void k_slots(const float* __restrict__ slots, const float* __restrict__ scale) {
    int m = blockIdx.x, tid = threadIdx.x;
    __shared__ float red[8];
    float ss = 0.f;
    for (int i = tid; i < DD; i += 256) { float v = slots[m * DD + i]; ss += v * v; }
    for (int o = 16; o; o >>= 1) ss += __shfl_down_sync(~0u, ss, o);
    if ((tid & 31) == 0) red[tid >> 5] = ss;
    __syncthreads();
    if (tid == 0) { float s = 0; for (int i = 0; i < 8; i++) s += red[i]; red[0] = s; }
    __syncthreads();
    float inv = scale[m] / fmaxf(sqrtf(red[0]), EPSF);
    for (int i = tid; i < DD; i += 256) g_sl[m * DD + i] = slots[m * DD + i] * inv;
}

// ---------------- K1: rmsnorm + token l2 inv-norm (192 thr, float4) -----------
__global__ void k_norm(const float* __restrict__ x, const float* __restrict__ nw) {
    int t = blockIdx.x, tid = threadIdx.x;
    __shared__ float red[6];
    __shared__ float bval;
    float4 v = ((const float4*)(x + (size_t)t * DD))[tid];
    float ss = v.x * v.x + v.y * v.y + v.z * v.z + v.w * v.w;
    for (int o = 16; o; o >>= 1) ss += __shfl_down_sync(~0u, ss, o);
    if ((tid & 31) == 0) red[tid >> 5] = ss;
    __syncthreads();
    if (tid == 0) {
        float s = 0; for (int i = 0; i < 6; i++) s += red[i];
        bval = rsqrtf(s / (float)DD + EPSF);
    }
    __syncthreads();
    float rstd = bval;
    float4 w = ((const float4*)nw)[tid];
    float4 a;
    a.x = v.x * rstd * w.x; a.y = v.y * rstd * w.y;
    a.z = v.z * rstd * w.z; a.w = v.w * rstd * w.w;
    ((float4*)(g_xn + (size_t)t * DD))[tid] = a;
    float s2 = a.x * a.x + a.y * a.y + a.z * a.z + a.w * a.w;
    for (int o = 16; o; o >>= 1) s2 += __shfl_down_sync(~0u, s2, o);
    __syncthreads();
    if ((tid & 31) == 0) red[tid >> 5] = s2;
    __syncthreads();
    if (tid == 0) {
        float s = 0; for (int i = 0; i < 6; i++) s += red[i];
        g_rn[t] = 1.f / fmaxf(sqrtf(s), EPSF);
    }
}

// ---------------- K2: logits (half out) ----------------------------------------
__global__ void k_logits() {
    int s = blockIdx.x * 128 + threadIdx.x;
    int h = blockIdx.y, b = blockIdx.z;
    __shared__ float4 sl4[MM][HD / 4];
    for (int i = threadIdx.x; i < MM * (HD / 4); i += 128) {
        int m = i / (HD / 4), d4 = i % (HD / 4);
        sl4[m][d4] = *(const float4*)&g_sl[m * DD + h * HD + d4 * 4];
    }
    __syncthreads();
    float rn = g_rn[b * SS + s];
    float4 tok[16];
    const float* xp = &g_xn[((size_t)(b * SS + s)) * DD + h * HD];
#pragma unroll
    for (int i = 0; i < 16; i++) {
        float4 v = *(const float4*)(xp + i * 4);
        v.x *= rn; v.y *= rn; v.z *= rn; v.w *= rn;
        tok[i] = v;
    }
    size_t lbase = (size_t)((b * HH + h) * MM) * SS + s;
    for (int m = 0; m < MM; m++) {
        float dot = 0.f;
#pragma unroll
        for (int i = 0; i < 16; i++) {
            float4 sv = sl4[m][i];
            dot += tok[i].x * sv.x + tok[i].y * sv.y + tok[i].z * sv.z + tok[i].w * sv.w;
        }
        g_lh[lbase + (size_t)m * SS] = __float2half(dot);
    }
}

// ---------------- K3: one-pass online softmax stats ---------------------------
__global__ void __launch_bounds__(128) k_stats() {
    int r = blockIdx.x, tid = threadIdx.x;
    const __half* row = g_lh + (size_t)r * SS;
    float4 raw[4];
    const float4* p = (const float4*)(row + tid * 32);
#pragma unroll
    for (int q = 0; q < 4; q++) raw[q] = p[q];
    float v[32];
#pragma unroll
    for (int q = 0; q < 4; q++) {
        const __half2* h2 = (const __half2*)&raw[q];
#pragma unroll
        for (int j = 0; j < 4; j++) {
            float2 f = __half22float2(h2[j]);
            v[q * 8 + j * 2] = f.x; v[q * 8 + j * 2 + 1] = f.y;
        }
    }
    float mx = -1e30f;
#pragma unroll
    for (int i = 0; i < 32; i++) mx = fmaxf(mx, v[i]);
    __shared__ float red[4];
    __shared__ float smx;
    for (int o = 16; o; o >>= 1) mx = fmaxf(mx, __shfl_down_sync(~0u, mx, o));
    if ((tid & 31) == 0) red[tid >> 5] = mx;
    __syncthreads();
    if (tid == 0) smx = fmaxf(fmaxf(red[0], red[1]), fmaxf(red[2], red[3]));
    __syncthreads();
    float gmx = smx;
    float sm = 0.f;
#pragma unroll
    for (int i = 0; i < 32; i++) sm += __expf(v[i] - gmx);
    for (int o = 16; o; o >>= 1) sm += __shfl_down_sync(~0u, sm, o);
    __syncthreads();
    if ((tid & 31) == 0) red[tid >> 5] = sm;
    __syncthreads();
    if (tid == 0) {
        g_rmax[r] = gmx;
        g_rsum[r] = red[0] + red[1] + red[2] + red[3];
    }
}

// ---------------- K4: init (zero g_y, bias-broadcast hid & y2) ------------------
__global__ void k_binit(const float* __restrict__ b1, const float* __restrict__ b2) {
    int i = blockIdx.x * 256 + threadIdx.x;
    const int N1 = BB * MM * DD;
    const int N2 = BB * MM * FF;
    if (i < N1) g_y[i] = 0.f;
    else if (i < N1 + N2) { int k = i - N1; g_hid[k] = b1[k % (MM * FF)]; }
    else { int k = i - N1 - N2; g_y2[k] = b2[k % (MM * DD)]; }
}

// ---------------- K5: dispatch -------------------------------------------------
__global__ void __launch_bounds__(128) k_disp() {
    int ch = blockIdx.x, h = blockIdx.y, b = blockIdx.z;
    int tid = threadIdx.x;
    int sp = tid >> 6;           // s parity
    int w  = tid & 63;
    int mg = w >> 4;             // 4 groups of 16 m
    int dg = w & 15;             // 16 groups of 4 d
    __shared__ float pT[64][68];
    __shared__ float xts[64][68];
    __shared__ float smax[64], sinv[64];
    if (tid < 64) {
        int r = (b * HH + h) * MM + tid;
        smax[tid] = g_rmax[r];
        sinv[tid] = 1.f / g_rsum[r];
    }
    float4 acc[16];
#pragma unroll
    for (int j = 0; j < 16; j++) acc[j] = make_float4(0.f, 0.f, 0.f, 0.f);
    size_t lbh = (size_t)((b * HH + h) * MM) * SS;
    for (int tile = 0; tile < 8; tile++) {
        int s0 = (ch * 8 + tile) * 64;
        __syncthreads();
        for (int i = tid; i < 64 * 32; i += 128) {
            int m = i >> 5, s2 = i & 31;
            __half2 hv = *(const __half2*)&g_lh[lbh + (size_t)m * SS + s0 + 2 * s2];
            float2 f = __half22float2(hv);
            float mmax = smax[m], minv = sinv[m];
            pT[2 * s2][m]     = __expf(f.x - mmax) * minv;
            pT[2 * s2 + 1][m] = __expf(f.y - mmax) * minv;
        }
        for (int i = tid; i < 64 * 16; i += 128) {
            int s = i >> 4, d4 = i & 15;
            *(float4*)&xts[s][d4 * 4] =
                *(const float4*)&g_xn[((size_t)(b * SS + s0 + s)) * DD + h * HD + d4 * 4];
        }
        __syncthreads();
        for (int s = sp; s < 64; s += 2) {
            float4 xv = *(const float4*)&xts[s][dg * 4];
#pragma unroll
            for (int j = 0; j < 4; j++) {
                float4 pv = *(const float4*)&pT[s][mg * 16 + j * 4];
                acc[j*4+0].x += pv.x*xv.x; acc[j*4+0].y += pv.x*xv.y; acc[j*4+0].z += pv.x*xv.z; acc[j*4+0].w += pv.x*xv.w;
                acc[j*4+1].x += pv.y*xv.x; acc[j*4+1].y += pv.y*xv.y; acc[j*4+1].z += pv.y*xv.z; acc[j*4+1].w += pv.y*xv.w;
                acc[j*4+2].x += pv.z*xv.x; acc[j*4+2].y += pv.z*xv.y; acc[j*4+2].z += pv.z*xv.z; acc[j*4+2].w += pv.z*xv.w;
                acc[j*4+3].x += pv.w*xv.x; acc[j*4+3].y += pv.w*xv.y; acc[j*4+3].z += pv.w*xv.z; acc[j*4+3].w += pv.w*xv.w;
            }
        }
    }
#pragma unroll
    for (int ml = 0; ml < 16; ml++) {
        int m = mg * 16 + ml;
        float* base = &g_y[((size_t)(b * MM + m)) * DD + h * HD + dg * 4];
        atomicAdd(base + 0, acc[ml].x);
        atomicAdd(base + 1, acc[ml].y);
        atomicAdd(base + 2, acc[ml].z);
        atomicAdd(base + 3, acc[ml].w);
    }
}

// ---------------- K6: fc1 (split-K, atomic accumulate) --------------------------
__global__ void __launch_bounds__(256) k_fc1(const float* __restrict__ w1) {
    int fblk = blockIdx.x, m = blockIdx.y, kc = blockIdx.z;
    int tid = threadIdx.x;
    int f = fblk * 1024 + tid * 4;
    __shared__ float ys[8][192];
    for (int i = tid; i < 8 * 192; i += 256) {
        int b = i / 192, k = i % 192;
        ys[b][k] = g_y[((size_t)(b * MM + m)) * DD + kc * 192 + k];
    }
    __syncthreads();
    float4 acc[8];
#pragma unroll
    for (int b = 0; b < 8; b++) acc[b] = make_float4(0.f, 0.f, 0.f, 0.f);
    const float* wp = w1 + (size_t)m * DD * FF + (size_t)(kc * 192) * FF + f;
#pragma unroll 4
    for (int k = 0; k < 192; k++) {
        float4 wv = *(const float4*)(wp + (size_t)k * FF);
#pragma unroll
        for (int b = 0; b < 8; b++) {
            float yv = ys[b][k];
            acc[b].x += yv * wv.x; acc[b].y += yv * wv.y;
            acc[b].z += yv * wv.z; acc[b].w += yv * wv.w;
        }
    }
#pragma unroll
    for (int b = 0; b < 8; b++) {
        float* hp = &g_hid[((size_t)(b * MM + m)) * FF + f];
        atomicAdd(hp + 0, acc[b].x);
        atomicAdd(hp + 1, acc[b].y);
        atomicAdd(hp + 2, acc[b].z);
        atomicAdd(hp + 3, acc[b].w);
    }
}

// ---------------- K7: fc2 (gelu on load, split-K, atomic accumulate) ------------
__global__ void __launch_bounds__(192) k_fc2(const float* __restrict__ w2) {
    int m = blockIdx.x, kc = blockIdx.y;
    int tid = threadIdx.x;
    int d = tid * 4;
    __shared__ float hs[8][384];
    for (int i = tid; i < 8 * 384; i += 192) {
        int b = i / 384, k = i % 384;
        float v = g_hid[((size_t)(b * MM + m)) * FF + kc * 384 + k];
        hs[b][k] = 0.5f * v * (1.f + erff(v * 0.70710678118654752f));
    }
    __syncthreads();
    float4 acc[8];
#pragma unroll
    for (int b = 0; b < 8; b++) acc[b] = make_float4(0.f, 0.f, 0.f, 0.f);
    const float* wp = w2 + (size_t)m * FF * DD + (size_t)(kc * 384) * DD + d;
#pragma unroll 4
    for (int k = 0; k < 384; k++) {
        float4 wv = *(const float4*)(wp + (size_t)k * DD);
#pragma unroll
        for (int b = 0; b < 8; b++) {
            float hv = hs[b][k];
            acc[b].x += hv * wv.x; acc[b].y += hv * wv.y;
            acc[b].z += hv * wv.z; acc[b].w += hv * wv.w;
        }
    }
#pragma unroll
    for (int b = 0; b < 8; b++) {
        float* yp = &g_y2[((size_t)(b * MM + m)) * DD + d];
        atomicAdd(yp + 0, acc[b].x);
        atomicAdd(yp + 1, acc[b].y);
        atomicAdd(yp + 2, acc[b].z);
        atomicAdd(yp + 3, acc[b].w);
    }
}

// ---------------- K8: combine ---------------------------------------------------
__global__ void __launch_bounds__(256) k_comb(float* __restrict__ out) {
    int sb = blockIdx.x, h = blockIdx.y, b = blockIdx.z;
    int s0 = sb * 64;
    int tid = threadIdx.x;
    __shared__ float pSm[64][68];    // [m][s]
    __shared__ float y2s[64][68];    // [m][d]
    __shared__ float pmax[2][64], psum[2][64], smx[64], sinvs[64];
    size_t lbh = (size_t)((b * HH + h) * MM) * SS;
    for (int i = tid; i < 64 * 32; i += 256) {
        int m = i >> 5, s2 = i & 31;
        __half2 hv = *(const __half2*)&g_lh[lbh + (size_t)m * SS + s0 + 2 * s2];
        float2 f = __half22float2(hv);
        pSm[m][2 * s2] = f.x; pSm[m][2 * s2 + 1] = f.y;
    }
    for (int i = tid; i < 64 * 16; i += 256) {
        int m = i >> 4, d4 = i & 15;
        *(float4*)&y2s[m][d4 * 4] =
            *(const float4*)&g_y2[((size_t)(b * MM + m)) * DD + h * HD + d4 * 4];
    }
    __syncthreads();
    if (tid < 128) {
        int t = tid & 63, mh = tid >> 6;
        float mx = -1e30f;
#pragma unroll 8
        for (int mm = 0; mm < 32; mm++) mx = fmaxf(mx, pSm[mh * 32 + mm][t]);
        pmax[mh][t] = mx;
    }
    __syncthreads();
    if (tid < 64) smx[tid] = fmaxf(pmax[0][tid], pmax[1][tid]);
    __syncthreads();
    if (tid < 128) {
        int t = tid & 63, mh = tid >> 6;
        float mx = smx[t], sm = 0.f;
#pragma unroll 8
        for (int mm = 0; mm < 32; mm++) {
            float e = __expf(pSm[mh * 32 + mm][t] - mx);
            pSm[mh * 32 + mm][t] = e;
            sm += e;
        }
        psum[mh][t] = sm;
    }
    __syncthreads();
    if (tid < 64) sinvs[tid] = 1.f / (psum[0][tid] + psum[1][tid]);
    __syncthreads();
    int s4 = tid >> 4, dg = tid & 15;
    float4 acc[4];
#pragma unroll
    for (int j = 0; j < 4; j++) acc[j] = make_float4(0.f, 0.f, 0.f, 0.f);
#pragma unroll 4
    for (int m = 0; m < 64; m++) {
        float4 pv = *(const float4*)&pSm[m][s4 * 4];
        float4 yv = *(const float4*)&y2s[m][dg * 4];
        acc[0].x += pv.x*yv.x; acc[0].y += pv.x*yv.y; acc[0].z += pv.x*yv.z; acc[0].w += pv.x*yv.w;
        acc[1].x += pv.y*yv.x; acc[1].y += pv.y*yv.y; acc[1].z += pv.y*yv.z; acc[1].w += pv.y*yv.w;
        acc[2].x += pv.z*yv.x; acc[2].y += pv.z*yv.y; acc[2].z += pv.z*yv.z; acc[2].w += pv.z*yv.w;
        acc[3].x += pv.w*yv.x; acc[3].y += pv.w*yv.y; acc[3].z += pv.w*yv.z; acc[3].w += pv.w*yv.w;
    }
#pragma unroll
    for (int ss = 0; ss < 4; ss++) {
        int s = s0 + s4 * 4 + ss;
        float inv = sinvs[s4 * 4 + ss];
        float4 o;
        o.x = acc[ss].x * inv; o.y = acc[ss].y * inv;
        o.z = acc[ss].z * inv; o.w = acc[ss].w * inv;
        *(float4*)&out[((size_t)(b * SS + s)) * DD + h * HD + dg * 4] = o;
    }
}

// ---------------- launch --------------------------------------------------------
extern "C" void kernel_launch(void* const* d_in, const int* in_sizes, int n_in,
                              void* d_out, int out_size) {
    const float* x      = (const float*)d_in[0];
    const float* slots  = (const float*)d_in[1];
    const float* scale  = (const float*)d_in[2];
    const float* fc1_w  = (const float*)d_in[3];
    const float* fc1_b  = (const float*)d_in[4];
    const float* fc2_w  = (const float*)d_in[5];
    const float* fc2_b  = (const float*)d_in[6];
    const float* norm_w = (const float*)d_in[7];
    float* out = (float*)d_out;

    k_slots<<<MM, 256>>>(slots, scale);
    k_norm<<<BB * SS, 192>>>(x, norm_w);
    k_logits<<<dim3(SS / 128, HH, BB), 128>>>();
    k_stats<<<BB * HH * MM, 128>>>();
    k_binit<<<(BB * MM * (2 * DD + FF)) / 256, 256>>>(fc1_b, fc2_b);
    k_disp<<<dim3(8, HH, BB), 128>>>();
    k_fc1<<<dim3(3, MM, 4), 256>>>(fc1_w);
    k_fc2<<<dim3(MM, 8), 192>>>(fc2_w);
    k_comb<<<dim3(SS / 64, HH, BB), 256>>>(out);
}

// round 3
// speedup vs baseline: 1.8433x; 1.0451x over previous
#include <cuda_runtime.h>
#include <cuda_fp16.h>
#include <math.h>

#define BB 8
#define SS 4096
#define DD 768
#define MM 64
#define FF 3072
#define HH 12
#define HD 64
#define EPSF 1e-5f

typedef unsigned long long ull;

__device__ __forceinline__ ull pk2(float lo, float hi) {
    ull r;
    asm("mov.b64 %0, {%1, %2};" : "=l"(r) : "f"(lo), "f"(hi));
    return r;
}
__device__ __forceinline__ void upk2(ull v, float& lo, float& hi) {
    asm("mov.b64 {%0, %1}, %2;" : "=f"(lo), "=f"(hi) : "l"(v));
}
#define FMA2(a, x, y) asm("fma.rn.f32x2 %0, %1, %2, %0;" : "+l"(a) : "l"(x), "l"(y))

// ---------------- scratch -----------------------------------------------------
__device__ float  g_sl[MM * DD];
__device__ float  g_xn[BB * SS * DD];
__device__ float  g_rn[BB * SS];
__device__ __half g_lh[(size_t)BB * HH * MM * SS];
__device__ float  g_rmax[BB * HH * MM];
__device__ float  g_rsum[BB * HH * MM];
__device__ float  g_y[BB * MM * DD];
__device__ float  g_hid[(size_t)BB * MM * FF];
__device__ float  g_y2[BB * MM * DD];

// ---------------- K0: slots ---------------------------------------------------
__global__ void k_slots(const float* __restrict__ slots, const float* __restrict__ scale) {
    int m = blockIdx.x, tid = threadIdx.x;
    __shared__ float red[8];
    float ss = 0.f;
    for (int i = tid; i < DD; i += 256) { float v = slots[m * DD + i]; ss += v * v; }
    for (int o = 16; o; o >>= 1) ss += __shfl_down_sync(~0u, ss, o);
    if ((tid & 31) == 0) red[tid >> 5] = ss;
    __syncthreads();
    if (tid == 0) { float s = 0; for (int i = 0; i < 8; i++) s += red[i]; red[0] = s; }
    __syncthreads();
    float inv = scale[m] / fmaxf(sqrtf(red[0]), EPSF);
    for (int i = tid; i < DD; i += 256) g_sl[m * DD + i] = slots[m * DD + i] * inv;
}

// ---------------- K1: rmsnorm + token l2 inv-norm ------------------------------
__global__ void k_norm(const float* __restrict__ x, const float* __restrict__ nw) {
    int t = blockIdx.x, tid = threadIdx.x;
    __shared__ float red[6];
    __shared__ float bval;
    float4 v = ((const float4*)(x + (size_t)t * DD))[tid];
    float ss = v.x * v.x + v.y * v.y + v.z * v.z + v.w * v.w;
    for (int o = 16; o; o >>= 1) ss += __shfl_down_sync(~0u, ss, o);
    if ((tid & 31) == 0) red[tid >> 5] = ss;
    __syncthreads();
    if (tid == 0) {
        float s = 0; for (int i = 0; i < 6; i++) s += red[i];
        bval = rsqrtf(s / (float)DD + EPSF);
    }
    __syncthreads();
    float rstd = bval;
    float4 w = ((const float4*)nw)[tid];
    float4 a;
    a.x = v.x * rstd * w.x; a.y = v.y * rstd * w.y;
    a.z = v.z * rstd * w.z; a.w = v.w * rstd * w.w;
    ((float4*)(g_xn + (size_t)t * DD))[tid] = a;
    float s2 = a.x * a.x + a.y * a.y + a.z * a.z + a.w * a.w;
    for (int o = 16; o; o >>= 1) s2 += __shfl_down_sync(~0u, s2, o);
    __syncthreads();
    if ((tid & 31) == 0) red[tid >> 5] = s2;
    __syncthreads();
    if (tid == 0) {
        float s = 0; for (int i = 0; i < 6; i++) s += red[i];
        g_rn[t] = 1.f / fmaxf(sqrtf(s), EPSF);
    }
}

// ---------------- K2: logits, 2 tokens/thread, f32x2 ---------------------------
__global__ void __launch_bounds__(128) k_logits() {
    int t0 = blockIdx.x * 256 + threadIdx.x;   // token A; token B = t0+128
    int h = blockIdx.y, b = blockIdx.z;
    __shared__ float slS[MM][HD];
    for (int i = threadIdx.x; i < MM * (HD / 4); i += 128) {
        int m = i >> 4, d4 = i & 15;
        *(float4*)&slS[m][d4 * 4] = *(const float4*)&g_sl[m * DD + h * HD + d4 * 4];
    }
    __syncthreads();
    ull ta[32], tb[32];
    {
        float rn0 = g_rn[b * SS + t0];
        const float* xp = &g_xn[((size_t)(b * SS + t0)) * DD + h * HD];
#pragma unroll
        for (int i = 0; i < 16; i++) {
            float4 v = *(const float4*)(xp + i * 4);
            ta[2 * i] = pk2(v.x * rn0, v.y * rn0);
            ta[2 * i + 1] = pk2(v.z * rn0, v.w * rn0);
        }
        float rn1 = g_rn[b * SS + t0 + 128];
        const float* xq = &g_xn[((size_t)(b * SS + t0 + 128)) * DD + h * HD];
#pragma unroll
        for (int i = 0; i < 16; i++) {
            float4 v = *(const float4*)(xq + i * 4);
            tb[2 * i] = pk2(v.x * rn1, v.y * rn1);
            tb[2 * i + 1] = pk2(v.z * rn1, v.w * rn1);
        }
    }
    size_t lbase = (size_t)((b * HH + h) * MM) * SS;
    for (int m = 0; m < MM; m++) {
        ull a0 = 0, a1 = 0, c0 = 0, c1 = 0;
#pragma unroll
        for (int j = 0; j < 16; j++) {
            float4 sv = *(const float4*)&slS[m][j * 4];
            ull s0 = pk2(sv.x, sv.y), s1 = pk2(sv.z, sv.w);
            FMA2(a0, ta[2 * j], s0); FMA2(a1, ta[2 * j + 1], s1);
            FMA2(c0, tb[2 * j], s0); FMA2(c1, tb[2 * j + 1], s1);
        }
        float p0, p1, q0, q1, r0, r1, u0, u1;
        upk2(a0, p0, p1); upk2(a1, q0, q1);
        upk2(c0, r0, r1); upk2(c1, u0, u1);
        g_lh[lbase + (size_t)m * SS + t0]       = __float2half((p0 + p1) + (q0 + q1));
        g_lh[lbase + (size_t)m * SS + t0 + 128] = __float2half((r0 + r1) + (u0 + u1));
    }
}

// ---------------- K3: one-pass softmax stats -----------------------------------
__global__ void __launch_bounds__(128) k_stats() {
    int r = blockIdx.x, tid = threadIdx.x;
    const __half* row = g_lh + (size_t)r * SS;
    float4 raw[4];
    const float4* p = (const float4*)(row + tid * 32);
#pragma unroll
    for (int q = 0; q < 4; q++) raw[q] = p[q];
    float v[32];
#pragma unroll
    for (int q = 0; q < 4; q++) {
        const __half2* h2 = (const __half2*)&raw[q];
#pragma unroll
        for (int j = 0; j < 4; j++) {
            float2 f = __half22float2(h2[j]);
            v[q * 8 + j * 2] = f.x; v[q * 8 + j * 2 + 1] = f.y;
        }
    }
    float mx = -1e30f;
#pragma unroll
    for (int i = 0; i < 32; i++) mx = fmaxf(mx, v[i]);
    __shared__ float red[4];
    __shared__ float smxv;
    for (int o = 16; o; o >>= 1) mx = fmaxf(mx, __shfl_down_sync(~0u, mx, o));
    if ((tid & 31) == 0) red[tid >> 5] = mx;
    __syncthreads();
    if (tid == 0) smxv = fmaxf(fmaxf(red[0], red[1]), fmaxf(red[2], red[3]));
    __syncthreads();
    float gmx = smxv;
    float sm = 0.f;
#pragma unroll
    for (int i = 0; i < 32; i++) sm += __expf(v[i] - gmx);
    for (int o = 16; o; o >>= 1) sm += __shfl_down_sync(~0u, sm, o);
    __syncthreads();
    if ((tid & 31) == 0) red[tid >> 5] = sm;
    __syncthreads();
    if (tid == 0) {
        g_rmax[r] = gmx;
        g_rsum[r] = red[0] + red[1] + red[2] + red[3];
    }
}

// ---------------- K4: init -----------------------------------------------------
__global__ void k_binit(const float* __restrict__ b1, const float* __restrict__ b2) {
    int i = blockIdx.x * 256 + threadIdx.x;
    const int N1 = BB * MM * DD;
    const int N2 = BB * MM * FF;
    if (i < N1) g_y[i] = 0.f;
    else if (i < N1 + N2) { int k = i - N1; g_hid[k] = b1[k % (MM * FF)]; }
    else { int k = i - N1 - N2; g_y2[k] = b2[k % (MM * DD)]; }
}

// ---------------- K5: dispatch, f32x2 -------------------------------------------
__global__ void __launch_bounds__(128) k_disp() {
    int ch = blockIdx.x, h = blockIdx.y, b = blockIdx.z;
    int tid = threadIdx.x;
    int sp = tid >> 6;
    int w  = tid & 63;
    int mg = w >> 4;
    int dg = w & 15;
    __shared__ float pT[64][68];
    __shared__ float xts[64][68];
    __shared__ float smax[64], sinv[64];
    if (tid < 64) {
        int r = (b * HH + h) * MM + tid;
        smax[tid] = g_rmax[r];
        sinv[tid] = 1.f / g_rsum[r];
    }
    ull accL[16], accH[16];
#pragma unroll
    for (int j = 0; j < 16; j++) { accL[j] = 0ull; accH[j] = 0ull; }
    size_t lbh = (size_t)((b * HH + h) * MM) * SS;
    for (int tile = 0; tile < 8; tile++) {
        int s0 = (ch * 8 + tile) * 64;
        __syncthreads();
        for (int i = tid; i < 64 * 32; i += 128) {
            int m = i >> 5, s2 = i & 31;
            __half2 hv = *(const __half2*)&g_lh[lbh + (size_t)m * SS + s0 + 2 * s2];
            float2 f = __half22float2(hv);
            float mmax = smax[m], minv = sinv[m];
            pT[2 * s2][m]     = __expf(f.x - mmax) * minv;
            pT[2 * s2 + 1][m] = __expf(f.y - mmax) * minv;
        }
        for (int i = tid; i < 64 * 16; i += 128) {
            int s = i >> 4, d4 = i & 15;
            *(float4*)&xts[s][d4 * 4] =
                *(const float4*)&g_xn[((size_t)(b * SS + s0 + s)) * DD + h * HD + d4 * 4];
        }
        __syncthreads();
#pragma unroll 2
        for (int s = sp; s < 64; s += 2) {
            float4 xv = *(const float4*)&xts[s][dg * 4];
            ull xlo = pk2(xv.x, xv.y), xhi = pk2(xv.z, xv.w);
#pragma unroll
            for (int j = 0; j < 4; j++) {
                float4 pv = *(const float4*)&pT[s][mg * 16 + j * 4];
                ull p0 = pk2(pv.x, pv.x), p1 = pk2(pv.y, pv.y);
                ull p2 = pk2(pv.z, pv.z), p3 = pk2(pv.w, pv.w);
                FMA2(accL[j * 4 + 0], p0, xlo); FMA2(accH[j * 4 + 0], p0, xhi);
                FMA2(accL[j * 4 + 1], p1, xlo); FMA2(accH[j * 4 + 1], p1, xhi);
                FMA2(accL[j * 4 + 2], p2, xlo); FMA2(accH[j * 4 + 2], p2, xhi);
                FMA2(accL[j * 4 + 3], p3, xlo); FMA2(accH[j * 4 + 3], p3, xhi);
            }
        }
    }
#pragma unroll
    for (int ml = 0; ml < 16; ml++) {
        int m = mg * 16 + ml;
        float a0, a1, a2, a3;
        upk2(accL[ml], a0, a1); upk2(accH[ml], a2, a3);
        float* base = &g_y[((size_t)(b * MM + m)) * DD + h * HD + dg * 4];
        atomicAdd(base + 0, a0);
        atomicAdd(base + 1, a1);
        atomicAdd(base + 2, a2);
        atomicAdd(base + 3, a3);
    }
}

// ---------------- K6: fc1, f32x2 -------------------------------------------------
__global__ void __launch_bounds__(256) k_fc1(const float* __restrict__ w1) {
    int fblk = blockIdx.x, m = blockIdx.y, kc = blockIdx.z;
    int tid = threadIdx.x;
    int f = fblk * 1024 + tid * 4;
    __shared__ float ysT[192][12];   // [k][b], padded rows 48B (16B aligned)
    for (int i = tid; i < 8 * 192; i += 256) {
        int bb = i / 192, k = i % 192;
        ysT[k][bb] = g_y[((size_t)(bb * MM + m)) * DD + kc * 192 + k];
    }
    __syncthreads();
    ull accL[8], accH[8];
#pragma unroll
    for (int bb = 0; bb < 8; bb++) { accL[bb] = 0ull; accH[bb] = 0ull; }
    const float* wp = w1 + (size_t)m * DD * FF + (size_t)(kc * 192) * FF + f;
#pragma unroll 4
    for (int k = 0; k < 192; k++) {
        float4 wv = *(const float4*)(wp + (size_t)k * FF);
        ull wlo = pk2(wv.x, wv.y), whi = pk2(wv.z, wv.w);
        float4 ya = *(const float4*)&ysT[k][0];
        float4 yb = *(const float4*)&ysT[k][4];
        ull y0 = pk2(ya.x, ya.x), y1 = pk2(ya.y, ya.y), y2 = pk2(ya.z, ya.z), y3 = pk2(ya.w, ya.w);
        ull y4 = pk2(yb.x, yb.x), y5 = pk2(yb.y, yb.y), y6 = pk2(yb.z, yb.z), y7 = pk2(yb.w, yb.w);
        FMA2(accL[0], y0, wlo); FMA2(accH[0], y0, whi);
        FMA2(accL[1], y1, wlo); FMA2(accH[1], y1, whi);
        FMA2(accL[2], y2, wlo); FMA2(accH[2], y2, whi);
        FMA2(accL[3], y3, wlo); FMA2(accH[3], y3, whi);
        FMA2(accL[4], y4, wlo); FMA2(accH[4], y4, whi);
        FMA2(accL[5], y5, wlo); FMA2(accH[5], y5, whi);
        FMA2(accL[6], y6, wlo); FMA2(accH[6], y6, whi);
        FMA2(accL[7], y7, wlo); FMA2(accH[7], y7, whi);
    }
#pragma unroll
    for (int bb = 0; bb < 8; bb++) {
        float a0, a1, a2, a3;
        upk2(accL[bb], a0, a1); upk2(accH[bb], a2, a3);
        float* hp = &g_hid[((size_t)(bb * MM + m)) * FF + f];
        atomicAdd(hp + 0, a0);
        atomicAdd(hp + 1, a1);
        atomicAdd(hp + 2, a2);
        atomicAdd(hp + 3, a3);
    }
}

// ---------------- K7: fc2 (gelu on load), f32x2 ----------------------------------
__global__ void __launch_bounds__(192) k_fc2(const float* __restrict__ w2) {
    int m = blockIdx.x, kc = blockIdx.y;
    int tid = threadIdx.x;
    int d = tid * 4;
    __shared__ float hsT[384][12];
    for (int i = tid; i < 8 * 384; i += 192) {
        int bb = i / 384, k = i % 384;
        float v = g_hid[((size_t)(bb * MM + m)) * FF + kc * 384 + k];
        hsT[k][bb] = 0.5f * v * (1.f + erff(v * 0.70710678118654752f));
    }
    __syncthreads();
    ull accL[8], accH[8];
#pragma unroll
    for (int bb = 0; bb < 8; bb++) { accL[bb] = 0ull; accH[bb] = 0ull; }
    const float* wp = w2 + (size_t)m * FF * DD + (size_t)(kc * 384) * DD + d;
#pragma unroll 4
    for (int k = 0; k < 384; k++) {
        float4 wv = *(const float4*)(wp + (size_t)k * DD);
        ull wlo = pk2(wv.x, wv.y), whi = pk2(wv.z, wv.w);
        float4 ya = *(const float4*)&hsT[k][0];
        float4 yb = *(const float4*)&hsT[k][4];
        ull y0 = pk2(ya.x, ya.x), y1 = pk2(ya.y, ya.y), y2 = pk2(ya.z, ya.z), y3 = pk2(ya.w, ya.w);
        ull y4 = pk2(yb.x, yb.x), y5 = pk2(yb.y, yb.y), y6 = pk2(yb.z, yb.z), y7 = pk2(yb.w, yb.w);
        FMA2(accL[0], y0, wlo); FMA2(accH[0], y0, whi);
        FMA2(accL[1], y1, wlo); FMA2(accH[1], y1, whi);
        FMA2(accL[2], y2, wlo); FMA2(accH[2], y2, whi);
        FMA2(accL[3], y3, wlo); FMA2(accH[3], y3, whi);
        FMA2(accL[4], y4, wlo); FMA2(accH[4], y4, whi);
        FMA2(accL[5], y5, wlo); FMA2(accH[5], y5, whi);
        FMA2(accL[6], y6, wlo); FMA2(accH[6], y6, whi);
        FMA2(accL[7], y7, wlo); FMA2(accH[7], y7, whi);
    }
#pragma unroll
    for (int bb = 0; bb < 8; bb++) {
        float a0, a1, a2, a3;
        upk2(accL[bb], a0, a1); upk2(accH[bb], a2, a3);
        float* yp = &g_y2[((size_t)(bb * MM + m)) * DD + d];
        atomicAdd(yp + 0, a0);
        atomicAdd(yp + 1, a1);
        atomicAdd(yp + 2, a2);
        atomicAdd(yp + 3, a3);
    }
}

// ---------------- K8: combine, f32x2 ---------------------------------------------
__global__ void __launch_bounds__(128) k_comb(float* __restrict__ out) {
    int sb = blockIdx.x, h = blockIdx.y, b = blockIdx.z;
    int s0 = sb * 64;
    int tid = threadIdx.x;
    __shared__ float pSm[64][68];
    __shared__ float y2s[64][72];
    __shared__ float pmax[2][64], psum[2][64], smx[64], sinvs[64];
    size_t lbh = (size_t)((b * HH + h) * MM) * SS;
    for (int i = tid; i < 64 * 32; i += 128) {
        int m = i >> 5, s2 = i & 31;
        __half2 hv = *(const __half2*)&g_lh[lbh + (size_t)m * SS + s0 + 2 * s2];
        float2 f = __half22float2(hv);
        pSm[m][2 * s2] = f.x; pSm[m][2 * s2 + 1] = f.y;
    }
    for (int i = tid; i < 64 * 16; i += 128) {
        int m = i >> 4, d4 = i & 15;
        *(float4*)&y2s[m][d4 * 4] =
            *(const float4*)&g_y2[((size_t)(b * MM + m)) * DD + h * HD + d4 * 4];
    }
    __syncthreads();
    {
        int t = tid & 63, mh = tid >> 6;
        float mx = -1e30f;
#pragma unroll 8
        for (int mm = 0; mm < 32; mm++) mx = fmaxf(mx, pSm[mh * 32 + mm][t]);
        pmax[mh][t] = mx;
    }
    __syncthreads();
    if (tid < 64) smx[tid] = fmaxf(pmax[0][tid], pmax[1][tid]);
    __syncthreads();
    {
        int t = tid & 63, mh = tid >> 6;
        float mx = smx[t], sm = 0.f;
#pragma unroll 8
        for (int mm = 0; mm < 32; mm++) {
            float e = __expf(pSm[mh * 32 + mm][t] - mx);
            pSm[mh * 32 + mm][t] = e;
            sm += e;
        }
        psum[mh][t] = sm;
    }
    __syncthreads();
    if (tid < 64) sinvs[tid] = 1.f / (psum[0][tid] + psum[1][tid]);
    __syncthreads();
    int sg = tid >> 3, dgrp = tid & 7;      // 16 s-groups x 8 d-groups
    ull acc[4][4];
#pragma unroll
    for (int i = 0; i < 4; i++)
#pragma unroll
        for (int j = 0; j < 4; j++) acc[i][j] = 0ull;
#pragma unroll 4
    for (int m = 0; m < 64; m++) {
        float4 pv = *(const float4*)&pSm[m][sg * 4];
        ull pd0 = pk2(pv.x, pv.x), pd1 = pk2(pv.y, pv.y);
        ull pd2 = pk2(pv.z, pv.z), pd3 = pk2(pv.w, pv.w);
        float4 ya = *(const float4*)&y2s[m][dgrp * 8];
        float4 yb = *(const float4*)&y2s[m][dgrp * 8 + 4];
        ull yv0 = pk2(ya.x, ya.y), yv1 = pk2(ya.z, ya.w);
        ull yv2 = pk2(yb.x, yb.y), yv3 = pk2(yb.z, yb.w);
        FMA2(acc[0][0], pd0, yv0); FMA2(acc[0][1], pd0, yv1); FMA2(acc[0][2], pd0, yv2); FMA2(acc[0][3], pd0, yv3);
        FMA2(acc[1][0], pd1, yv0); FMA2(acc[1][1], pd1, yv1); FMA2(acc[1][2], pd1, yv2); FMA2(acc[1][3], pd1, yv3);
        FMA2(acc[2][0], pd2, yv0); FMA2(acc[2][1], pd2, yv1); FMA2(acc[2][2], pd2, yv2); FMA2(acc[2][3], pd2, yv3);
        FMA2(acc[3][0], pd3, yv0); FMA2(acc[3][1], pd3, yv1); FMA2(acc[3][2], pd3, yv2); FMA2(acc[3][3], pd3, yv3);
    }
#pragma unroll
    for (int ss = 0; ss < 4; ss++) {
        int s = s0 + sg * 4 + ss;
        float inv = sinvs[sg * 4 + ss];
        float o0, o1, o2, o3, o4, o5, o6, o7;
        upk2(acc[ss][0], o0, o1); upk2(acc[ss][1], o2, o3);
        upk2(acc[ss][2], o4, o5); upk2(acc[ss][3], o6, o7);
        float* op = &out[((size_t)(b * SS + s)) * DD + h * HD + dgrp * 8];
        float4 w0 = make_float4(o0 * inv, o1 * inv, o2 * inv, o3 * inv);
        float4 w1 = make_float4(o4 * inv, o5 * inv, o6 * inv, o7 * inv);
        *(float4*)(op + 0) = w0;
        *(float4*)(op + 4) = w1;
    }
}

// ---------------- launch --------------------------------------------------------
extern "C" void kernel_launch(void* const* d_in, const int* in_sizes, int n_in,
                              void* d_out, int out_size) {
    const float* x      = (const float*)d_in[0];
    const float* slots  = (const float*)d_in[1];
    const float* scale  = (const float*)d_in[2];
    const float* fc1_w  = (const float*)d_in[3];
    const float* fc1_b  = (const float*)d_in[4];
    const float* fc2_w  = (const float*)d_in[5];
    const float* fc2_b  = (const float*)d_in[6];
    const float* norm_w = (const float*)d_in[7];
    float* out = (float*)d_out;

    k_slots<<<MM, 256>>>(slots, scale);
    k_norm<<<BB * SS, 192>>>(x, norm_w);
    k_logits<<<dim3(SS / 256, HH, BB), 128>>>();
    k_stats<<<BB * HH * MM, 128>>>();
    k_binit<<<(BB * MM * (2 * DD + FF)) / 256, 256>>>(fc1_b, fc2_b);
    k_disp<<<dim3(8, HH, BB), 128>>>();
    k_fc1<<<dim3(3, MM, 4), 256>>>(fc1_w);
    k_fc2<<<dim3(MM, 8), 192>>>(fc2_w);
    k_comb<<<dim3(SS / 64, HH, BB), 128>>>(out);
}